// round 16
// baseline (speedup 1.0000x reference)
#include <cuda_runtime.h>
#include <cuda_fp16.h>
#include <mma.h>
#include <stdint.h>

using namespace nvcuda;

#define D 128
#define MAX_N 50048
#define BKT_CAP 128                             // max in-degree (Poisson(12) tail ~1e-60)
#define THREADS 256
#define TILE_M 64

#define XW_LD 136
#define SMEM_XH (TILE_M * XW_LD * 2)            // 17408
#define SMEM_TOTAL (SMEM_XH + 128 * XW_LD * 2)  // + wh 34816 = 52224 (cs reuses)

// Scratch (device globals — no allocation). Self-cleaning: counters and g_cnt
// are zero at entry of every launch. Row n of g_hh is never written -> stays
// zero forever; used as padding target in the gather inner loop.
__device__ __half2 g_hh[(size_t)MAX_N * (D/2)]; // hh' = (x@W) * dis[row], fp16
__device__ __half  g_w16[D * D];                // W in fp16 (rebuilt每 launch)
__device__ float   g_dis[MAX_N];
__device__ int     g_cnt[MAX_N];
__device__ int     g_bkt[(size_t)MAX_N * BKT_CAP]; // src*64 (half2-unit offsets)
__device__ unsigned g_tile, g_work;             // work counters
__device__ unsigned g_bar1, g_bar2, g_done;     // grid barriers + done counter

// ---- grid barrier: all blocks co-resident (grid sized by occupancy) ----
__device__ __forceinline__ void gbar(unsigned* ctr, int grid) {
    __syncthreads();
    if (threadIdx.x == 0) {
        __threadfence();
        unsigned t = atomicAdd(ctr, 1) + 1;
        if (t < (unsigned)grid) {
            while (*((volatile unsigned*)ctr) < (unsigned)grid) __nanosleep(64);
        }
    }
    __syncthreads();
}

__global__ void k_prep(const float*, const int*, const float*, int, int, int);

// ---- program-load init (capture-safe): smem attr + co-resident grid size ----
struct Ctx {
    int grid;
    Ctx() {
        cudaFuncSetAttribute(k_prep, cudaFuncAttributeMaxDynamicSharedMemorySize,
                             SMEM_TOTAL);
        int dev = 0, sms = 148, occ = 2;
        cudaGetDevice(&dev);
        cudaDeviceGetAttribute(&sms, cudaDevAttrMultiProcessorCount, dev);
        cudaOccupancyMaxActiveBlocksPerMultiprocessor(&occ, k_prep, THREADS, SMEM_TOTAL);
        if (occ < 1) occ = 1;
        grid = sms * occ;
    }
};
static Ctx g_ctx;

// =======================================================================
// k_prep (persistent, co-resident):
//   B: bucket fill (stores src*64 offsets)
//   barrier
//   C: dis = rsqrt(cnt+1)  +  W -> fp16 conversion (once)
//   barrier
//   A: gemm tiles M=64 (wmma), epilogue hh' = h*dis (fp16)
//   control-state reset by last block
// =======================================================================
__global__ __launch_bounds__(THREADS, 2) void k_prep(
    const float* __restrict__ x, const int* __restrict__ ei,
    const float* __restrict__ W, int n, int e, int grid)
{
    extern __shared__ char smem[];
    __shared__ unsigned s_id;
    int tid = threadIdx.x;

    // ---------------- Phase B: bucket fill, dynamic chunks ----------------
    {
        int nchunks = (e + 1023) / 1024;        // 1024 edges = 256 thr * 4
        for (;;) {
            if (tid == 0) s_id = atomicAdd(&g_work, 1);
            __syncthreads();
            unsigned ch = s_id;
            __syncthreads();
            if (ch >= (unsigned)nchunks) break;
            int base = (int)ch * 1024 + (tid << 2);
            if (base + 3 < e) {
                int4 s4 = *(const int4*)(ei + base);
                int4 d4 = *(const int4*)(ei + e + base);
                int p0 = atomicAdd(&g_cnt[d4.x], 1);
                int p1 = atomicAdd(&g_cnt[d4.y], 1);
                int p2 = atomicAdd(&g_cnt[d4.z], 1);
                int p3 = atomicAdd(&g_cnt[d4.w], 1);
                g_bkt[(size_t)d4.x * BKT_CAP + p0] = s4.x << 6;   // src*64
                g_bkt[(size_t)d4.y * BKT_CAP + p1] = s4.y << 6;
                g_bkt[(size_t)d4.z * BKT_CAP + p2] = s4.z << 6;
                g_bkt[(size_t)d4.w * BKT_CAP + p3] = s4.w << 6;
            } else {
                for (int j = base; j < e; j++) {
                    int d = ei[e + j];
                    int pos = atomicAdd(&g_cnt[d], 1);
                    g_bkt[(size_t)d * BKT_CAP + pos] = ei[j] << 6;
                }
            }
        }
    }

    gbar(&g_bar1, grid);            // counts complete

    // ---------------- Phase C: dis + W->fp16 ----------------
    for (int i = blockIdx.x * THREADS + tid; i < n; i += grid * THREADS)
        g_dis[i] = rsqrtf((float)(g_cnt[i] + 1));
    for (int i = blockIdx.x * THREADS + tid; i < (D * D) / 2; i += grid * THREADS) {
        float2 v = ((const float2*)W)[i];
        ((__half2*)g_w16)[i] = __floats2half2_rn(v.x, v.y);
    }

    gbar(&g_bar2, grid);            // dis + w16 complete

    // ---------------- Phase A: gemm hh' = (x@W)*dis, M=64 tiles ----------------
    {
        __half* xh = (__half*)smem;                  // [64][XW_LD]
        __half* wh = (__half*)(smem + SMEM_XH);      // [128][XW_LD]
        float*  cs = (float*)smem;                   // reuse: [64][128] = 32KB
        int tiles = (n + TILE_M - 1) / TILE_M;

        for (;;) {
            if (tid == 0) s_id = atomicAdd(&g_tile, 1);
            __syncthreads();
            unsigned t = s_id;
            __syncthreads();
            if (t >= (unsigned)tiles) break;
            int row0 = (int)t * TILE_M;

            // stage x: 64 rows, convert f32->f16
#pragma unroll
            for (int it = 0; it < 8; it++) {
                int idx = it * 256 + tid;            // 2048 float4s
                int r = idx >> 5;
                int q = idx & 31;
                int gr = row0 + r;
                float4 v = make_float4(0.f, 0.f, 0.f, 0.f);
                if (gr < n) v = *(const float4*)(x + (size_t)gr * D + (q << 2));
                __half2* p = (__half2*)(xh + r * XW_LD + (q << 2));
                p[0] = __floats2half2_rn(v.x, v.y);
                p[1] = __floats2half2_rn(v.z, v.w);
            }
            // stage W: fp16 copy from g_w16 (no conversion)
#pragma unroll
            for (int it = 0; it < 8; it++) {
                int idx = it * 256 + tid;            // 2048 uint4s (8 halves each)
                int r = idx >> 4;
                int q = idx & 15;
                uint4 v = *(const uint4*)(g_w16 + r * D + (q << 3));
                *(uint4*)(wh + r * XW_LD + (q << 3)) = v;
            }
            __syncthreads();

            int wid = tid >> 5;
            int wm = wid & 3;                        // 16-row strip 0..3
            int wn = wid >> 2;                       // 64-col half 0..1

            wmma::fragment<wmma::accumulator, 16, 16, 16, float> c[4];
#pragma unroll
            for (int j = 0; j < 4; j++) wmma::fill_fragment(c[j], 0.0f);

#pragma unroll
            for (int k = 0; k < 8; k++) {
                wmma::fragment<wmma::matrix_a, 16, 16, 16, __half, wmma::row_major> a;
                wmma::fragment<wmma::matrix_b, 16, 16, 16, __half, wmma::row_major> bf[4];
                wmma::load_matrix_sync(a, xh + (wm * 16) * XW_LD + k * 16, XW_LD);
#pragma unroll
                for (int j = 0; j < 4; j++)
                    wmma::load_matrix_sync(bf[j], wh + (k * 16) * XW_LD + wn * 64 + j * 16, XW_LD);
#pragma unroll
                for (int j = 0; j < 4; j++)
                    wmma::mma_sync(c[j], a, bf[j], c[j]);
            }

            __syncthreads();
#pragma unroll
            for (int j = 0; j < 4; j++)
                wmma::store_matrix_sync(cs + (wm * 16) * 128 + wn * 64 + j * 16,
                                        c[j], 128, wmma::mem_row_major);
            __syncthreads();

            // epilogue: hh' = f32(C) * dis[row]
#pragma unroll
            for (int it = 0; it < 8; it++) {
                int idx = it * 256 + tid;
                int r = idx >> 5;
                int q = idx & 31;
                int gr = row0 + r;
                if (gr < n) {
                    float di = g_dis[gr];
                    float4 v = *(const float4*)(cs + r * 128 + (q << 2));
                    __half2* hp = (__half2*)(g_hh + (size_t)gr * (D / 2) + (q << 1));
                    hp[0] = __floats2half2_rn(v.x * di, v.y * di);
                    hp[1] = __floats2half2_rn(v.z * di, v.w * di);
                }
            }
            __syncthreads();        // cs dead before next iter overwrites xh/wh
        }
    }

    // ---------------- control-state reset by last-finishing block ----------------
    __syncthreads();
    if (tid == 0) {
        __threadfence();
        unsigned t = atomicAdd(&g_done, 1);
        if (t == (unsigned)grid - 1) {
            g_tile = 0;
            g_work = 0;
            g_bar1 = 0;
            g_bar2 = 0;
            __threadfence();
            g_done = 0;
        }
    }
}

// ---------------- gather: warp per dst; offset payload; 8-wide fp16 groups ----------------
// out[w] = (sum_{s in bkt(w)} hh'[s] + hh'[w]) * dis[w] + b
__global__ __launch_bounds__(256) void k_gather(const float* __restrict__ b,
                                                float* __restrict__ out, int n) {
    int w = (blockIdx.x * blockDim.x + threadIdx.x) >> 5;
    int lane = threadIdx.x & 31;
    if (w >= n) return;
    int cnt = g_cnt[w];
    float nd = g_dis[w];
    const int* brow = g_bkt + (size_t)w * BKT_CAP;
    int lo = lane << 1;                              // half2 lane offset

    // self-loop term hh'[w]
    float4 acc;
    {
        uint2 raw = *(const uint2*)(g_hh + ((size_t)w << 6) + lo);
        float2 f0 = __half22float2(*(const __half2*)&raw.x);
        float2 f1 = __half22float2(*(const __half2*)&raw.y);
        acc.x = f0.x; acc.y = f0.y; acc.z = f1.x; acc.w = f1.y;
    }

    const __half2 z2 = __float2half2_rn(0.f);
    int zoff = n << 6;                               // zero row offset
    int j = 0;
    while (j < cnt) {
        int batch = min(cnt - j, 32);
        int s = (lane < batch) ? brow[j + lane] : zoff;
        int t8 = (batch + 7) & ~7;
        for (int t = 0; t < t8; t += 8) {
            __half2 hA = z2, hB = z2;
#pragma unroll
            for (int u = 0; u < 8; u++) {
                int st = __shfl_sync(0xffffffffu, s, t + u);
                uint2 raw = *(const uint2*)(g_hh + st + lo);
                hA = __hadd2(hA, *(const __half2*)&raw.x);
                hB = __hadd2(hB, *(const __half2*)&raw.y);
            }
            float2 a0 = __half22float2(hA);
            float2 a1 = __half22float2(hB);
            acc.x += a0.x; acc.y += a0.y; acc.z += a1.x; acc.w += a1.y;
        }
        j += batch;
    }
    int c = lane << 2;
    float4 bv = *(const float4*)(b + c);
    float4 o;
    o.x = acc.x * nd + bv.x;
    o.y = acc.y * nd + bv.y;
    o.z = acc.z * nd + bv.z;
    o.w = acc.w * nd + bv.w;
    *(float4*)(out + (size_t)w * D + c) = o;

    if (lane == 0) g_cnt[w] = 0;                     // self-clean own row
}

extern "C" void kernel_launch(void* const* d_in, const int* in_sizes, int n_in,
                              void* d_out, int out_size) {
    const float* x  = (const float*)d_in[0];
    const int*   ei = (const int*)d_in[1];     // edge_index int32
    const float* W  = (const float*)d_in[2];
    const float* b  = (const float*)d_in[3];
    float* out = (float*)d_out;

    int n = in_sizes[0] / D;
    int e = in_sizes[1] / 2;

    k_prep<<<g_ctx.grid, THREADS, SMEM_TOTAL>>>(x, ei, W, n, e, g_ctx.grid);
    k_gather<<<(n * 32 + 255) / 256, 256>>>(b, out, n);
}

// round 17
// speedup vs baseline: 1.1338x; 1.1338x over previous
#include <cuda_runtime.h>
#include <cuda_fp16.h>
#include <mma.h>
#include <stdint.h>

using namespace nvcuda;

#define D 128
#define MAX_N 50048
#define BKT_CAP 128                             // max in-degree (Poisson(12) tail ~1e-60)
#define THREADS 256
#define TILE_M 64

#define XW_LD 136
#define SMEM_WH (128 * XW_LD * 2)               // 34816: W fp16, persistent per block
#define SMEM_XC (TILE_M * 128 * 4)              // 32768: xh (17408) / cs overlay
#define SMEM_TOTAL (SMEM_WH + SMEM_XC)          // 67584

// Scratch (device globals — no allocation). Self-cleaning: counters and g_cnt
// are zero at entry of every launch. Row n of g_hh is never written -> stays
// zero forever; used as padding target in the gather inner loop.
__device__ __half2 g_hh[(size_t)MAX_N * (D/2)]; // hh' = (x@W) * dis[row], fp16
__device__ __half  g_w16[D * D];                // W in fp16 (rebuilt per launch)
__device__ float   g_dis[MAX_N];
__device__ int     g_cnt[MAX_N];
__device__ int     g_bkt[(size_t)MAX_N * BKT_CAP];
__device__ unsigned g_tile, g_work;             // work counters
__device__ unsigned g_bar1, g_bar2, g_done;     // grid barriers + done counter

// ---- grid barrier: all blocks co-resident (grid sized by occupancy) ----
__device__ __forceinline__ void gbar(unsigned* ctr, int grid) {
    __syncthreads();
    if (threadIdx.x == 0) {
        __threadfence();
        unsigned t = atomicAdd(ctr, 1) + 1;
        if (t < (unsigned)grid) {
            while (*((volatile unsigned*)ctr) < (unsigned)grid) __nanosleep(64);
        }
    }
    __syncthreads();
}

__global__ void k_prep(const float*, const int*, const float*, int, int, int);

// ---- program-load init (capture-safe): smem attr + co-resident grid size ----
struct Ctx {
    int grid;
    Ctx() {
        cudaFuncSetAttribute(k_prep, cudaFuncAttributeMaxDynamicSharedMemorySize,
                             SMEM_TOTAL);
        int dev = 0, sms = 148, occ = 2;
        cudaGetDevice(&dev);
        cudaDeviceGetAttribute(&sms, cudaDevAttrMultiProcessorCount, dev);
        cudaOccupancyMaxActiveBlocksPerMultiprocessor(&occ, k_prep, THREADS, SMEM_TOTAL);
        if (occ < 1) occ = 1;
        grid = sms * occ;
    }
};
static Ctx g_ctx;

// =======================================================================
// k_prep (persistent, co-resident):
//   B: bucket fill (work-stolen chunks)
//   barrier
//   C: dis = rsqrt(cnt+1)  +  W -> fp16 (once, strided across grid)
//   barrier
//   A: load W into smem ONCE, then gemm tiles M=64 (wmma), hh' = h*dis
//   control-state reset by last block
// =======================================================================
__global__ __launch_bounds__(THREADS, 2) void k_prep(
    const float* __restrict__ x, const int* __restrict__ ei,
    const float* __restrict__ W, int n, int e, int grid)
{
    extern __shared__ char smem[];
    __shared__ unsigned s_id;
    int tid = threadIdx.x;

    // ---------------- Phase B: bucket fill, dynamic chunks ----------------
    {
        int nchunks = (e + 1023) / 1024;        // 1024 edges = 256 thr * 4
        for (;;) {
            if (tid == 0) s_id = atomicAdd(&g_work, 1);
            __syncthreads();
            unsigned ch = s_id;
            __syncthreads();
            if (ch >= (unsigned)nchunks) break;
            int base = (int)ch * 1024 + (tid << 2);
            if (base + 3 < e) {
                int4 s4 = *(const int4*)(ei + base);
                int4 d4 = *(const int4*)(ei + e + base);
                int p0 = atomicAdd(&g_cnt[d4.x], 1);
                int p1 = atomicAdd(&g_cnt[d4.y], 1);
                int p2 = atomicAdd(&g_cnt[d4.z], 1);
                int p3 = atomicAdd(&g_cnt[d4.w], 1);
                g_bkt[(size_t)d4.x * BKT_CAP + p0] = s4.x;
                g_bkt[(size_t)d4.y * BKT_CAP + p1] = s4.y;
                g_bkt[(size_t)d4.z * BKT_CAP + p2] = s4.z;
                g_bkt[(size_t)d4.w * BKT_CAP + p3] = s4.w;
            } else {
                for (int j = base; j < e; j++) {
                    int d = ei[e + j];
                    int pos = atomicAdd(&g_cnt[d], 1);
                    g_bkt[(size_t)d * BKT_CAP + pos] = ei[j];
                }
            }
        }
    }

    gbar(&g_bar1, grid);            // counts complete

    // ---------------- Phase C: dis + W->fp16 ----------------
    for (int i = blockIdx.x * THREADS + tid; i < n; i += grid * THREADS)
        g_dis[i] = rsqrtf((float)(g_cnt[i] + 1));
    for (int i = blockIdx.x * THREADS + tid; i < (D * D) / 2; i += grid * THREADS) {
        float2 v = ((const float2*)W)[i];
        ((__half2*)g_w16)[i] = __floats2half2_rn(v.x, v.y);
    }

    gbar(&g_bar2, grid);            // dis + w16 complete

    // ---------------- Phase A: gemm hh' = (x@W)*dis, W resident in smem ----------------
    {
        __half* wh = (__half*)smem;                  // [128][XW_LD], persistent
        __half* xh = (__half*)(smem + SMEM_WH);      // [64][XW_LD]
        float*  cs = (float*)(smem + SMEM_WH);       // overlay: [64][128]
        int tiles = (n + TILE_M - 1) / TILE_M;

        // load W fp16 into smem ONCE per block
#pragma unroll
        for (int it = 0; it < 8; it++) {
            int idx = it * 256 + tid;                // 2048 uint4s
            int r = idx >> 4;
            int q = idx & 15;
            uint4 v = *(const uint4*)(g_w16 + r * D + (q << 3));
            *(uint4*)(wh + r * XW_LD + (q << 3)) = v;
        }
        __syncthreads();

        for (;;) {
            if (tid == 0) s_id = atomicAdd(&g_tile, 1);
            __syncthreads();
            unsigned t = s_id;
            __syncthreads();
            if (t >= (unsigned)tiles) break;
            int row0 = (int)t * TILE_M;

            // stage x: 64 rows, convert f32->f16
#pragma unroll
            for (int it = 0; it < 8; it++) {
                int idx = it * 256 + tid;            // 2048 float4s
                int r = idx >> 5;
                int q = idx & 31;
                int gr = row0 + r;
                float4 v = make_float4(0.f, 0.f, 0.f, 0.f);
                if (gr < n) v = *(const float4*)(x + (size_t)gr * D + (q << 2));
                __half2* p = (__half2*)(xh + r * XW_LD + (q << 2));
                p[0] = __floats2half2_rn(v.x, v.y);
                p[1] = __floats2half2_rn(v.z, v.w);
            }
            __syncthreads();

            int wid = tid >> 5;
            int wm = wid & 3;                        // 16-row strip 0..3
            int wn = wid >> 2;                       // 64-col half 0..1

            wmma::fragment<wmma::accumulator, 16, 16, 16, float> c[4];
#pragma unroll
            for (int j = 0; j < 4; j++) wmma::fill_fragment(c[j], 0.0f);

#pragma unroll
            for (int k = 0; k < 8; k++) {
                wmma::fragment<wmma::matrix_a, 16, 16, 16, __half, wmma::row_major> a;
                wmma::fragment<wmma::matrix_b, 16, 16, 16, __half, wmma::row_major> bf[4];
                wmma::load_matrix_sync(a, xh + (wm * 16) * XW_LD + k * 16, XW_LD);
#pragma unroll
                for (int j = 0; j < 4; j++)
                    wmma::load_matrix_sync(bf[j], wh + (k * 16) * XW_LD + wn * 64 + j * 16, XW_LD);
#pragma unroll
                for (int j = 0; j < 4; j++)
                    wmma::mma_sync(c[j], a, bf[j], c[j]);
            }

            __syncthreads();                         // xh dead -> cs overlay safe
#pragma unroll
            for (int j = 0; j < 4; j++)
                wmma::store_matrix_sync(cs + (wm * 16) * 128 + wn * 64 + j * 16,
                                        c[j], 128, wmma::mem_row_major);
            __syncthreads();

            // epilogue: hh' = f32(C) * dis[row]
#pragma unroll
            for (int it = 0; it < 8; it++) {
                int idx = it * 256 + tid;
                int r = idx >> 5;
                int q = idx & 31;
                int gr = row0 + r;
                if (gr < n) {
                    float di = g_dis[gr];
                    float4 v = *(const float4*)(cs + r * 128 + (q << 2));
                    __half2* hp = (__half2*)(g_hh + (size_t)gr * (D / 2) + (q << 1));
                    hp[0] = __floats2half2_rn(v.x * di, v.y * di);
                    hp[1] = __floats2half2_rn(v.z * di, v.w * di);
                }
            }
            __syncthreads();        // cs dead before next iter overwrites xh
        }
    }

    // ---------------- control-state reset by last-finishing block ----------------
    __syncthreads();
    if (tid == 0) {
        __threadfence();
        unsigned t = atomicAdd(&g_done, 1);
        if (t == (unsigned)grid - 1) {
            g_tile = 0;
            g_work = 0;
            g_bar1 = 0;
            g_bar2 = 0;
            __threadfence();
            g_done = 0;
        }
    }
}

// ---------------- gather: warp per dst; prescaled fp16 payload; 4-wide groups ----------------
// out[w] = (sum_{s in bkt(w)} hh'[s] + hh'[w]) * dis[w] + b
__global__ __launch_bounds__(256) void k_gather(const float* __restrict__ b,
                                                float* __restrict__ out, int n) {
    int w = (blockIdx.x * blockDim.x + threadIdx.x) >> 5;
    int lane = threadIdx.x & 31;
    if (w >= n) return;
    int cnt = g_cnt[w];
    float nd = g_dis[w];
    const int* brow = g_bkt + (size_t)w * BKT_CAP;

    // self-loop term hh'[w] (fp32 accumulate)
    float4 acc;
    {
        uint2 raw = *(const uint2*)(g_hh + (size_t)w * (D / 2) + (lane << 1));
        float2 f0 = __half22float2(*(const __half2*)&raw.x);
        float2 f1 = __half22float2(*(const __half2*)&raw.y);
        acc.x = f0.x; acc.y = f0.y; acc.z = f1.x; acc.w = f1.y;
    }

    const __half2 z2 = __float2half2_rn(0.f);
    int j = 0;
    while (j < cnt) {
        int batch = min(cnt - j, 32);
        int s = (lane < batch) ? brow[j + lane] : n;   // n = zero row
        int t4 = (batch + 3) & ~3;
        for (int t = 0; t < t4; t += 4) {
            __half2 hA = z2, hB = z2;
#pragma unroll
            for (int u = 0; u < 4; u++) {
                int st = __shfl_sync(0xffffffffu, s, t + u);
                uint2 raw = *(const uint2*)(g_hh + (size_t)st * (D / 2) + (lane << 1));
                hA = __hadd2(hA, *(const __half2*)&raw.x);
                hB = __hadd2(hB, *(const __half2*)&raw.y);
            }
            float2 a0 = __half22float2(hA);
            float2 a1 = __half22float2(hB);
            acc.x += a0.x; acc.y += a0.y; acc.z += a1.x; acc.w += a1.y;
        }
        j += batch;
    }
    int c = lane << 2;
    float4 bv = *(const float4*)(b + c);
    float4 o;
    o.x = acc.x * nd + bv.x;
    o.y = acc.y * nd + bv.y;
    o.z = acc.z * nd + bv.z;
    o.w = acc.w * nd + bv.w;
    *(float4*)(out + (size_t)w * D + c) = o;

    if (lane == 0) g_cnt[w] = 0;                 // self-clean own row
}

extern "C" void kernel_launch(void* const* d_in, const int* in_sizes, int n_in,
                              void* d_out, int out_size) {
    const float* x  = (const float*)d_in[0];
    const int*   ei = (const int*)d_in[1];     // edge_index int32
    const float* W  = (const float*)d_in[2];
    const float* b  = (const float*)d_in[3];
    float* out = (float*)d_out;

    int n = in_sizes[0] / D;
    int e = in_sizes[1] / 2;

    k_prep<<<g_ctx.grid, THREADS, SMEM_TOTAL>>>(x, ei, W, n, e, g_ctx.grid);
    k_gather<<<(n * 32 + 255) / 256, 256>>>(b, out, n);
}